// round 16
// baseline (speedup 1.0000x reference)
#include <cuda_runtime.h>
#include <cstdint>

#define TOKENS 4096
#define HIDDEN 2048
#define INTER  768
#define NEXP   64
#define TOPK   8
#define NPAIRS (TOKENS*TOPK)
#define BK     32
#define STG    49152        // stage: A 16KB + B 2x16KB
#define KT1    (HIDDEN/BK)  // 64
#define KT2    (INTER/BK)   // 24
#define WSZ    100663296
#define PBMAX  320

#define NGAT   (PBMAX*KT1)      // 20480 gather bids
#define TPEREX 2304             // tiles per expert: 768 gate + 768 up + 768 down
#define NTILE  (NEXP*TPEREX)    // 147456
#define G1CNT  (16*6)
#define G1TOT  (G1CNT*NEXP)     // 6144
#define G2CNT  (16*8)
#define G2TOT  (G2CNT*NEXP)     // 8192
#define BID_TILE  NGAT
#define BID_G1    (NGAT+NTILE)
#define BID_G2    (BID_G1+G1TOT)
#define NBIDS     (BID_G2+G2TOT)

__device__ int   g_done[NEXP];
__device__ int   g_tgu[NEXP];
__device__ int   g_td[NEXP];
__device__ int   g_gat[NEXP];
__device__ int   g_counts[NEXP];
__device__ int   g_offsets[NEXP+1];
__device__ int   g_poff[NEXP+1];
__device__ int   g_cursor[NEXP];
__device__ int   g_pair_e[NPAIRS];
__device__ float g_pair_w[NPAIRS];
__device__ int   g_row_token[NPAIRS];
__device__ float g_row_weight[NPAIRS];
__device__ int   g_s2p[NPAIRS];
__device__ float g_act[(size_t)PBMAX * 128 * INTER];    // tiled [pb][kk24][16KB]
__device__ float g_pout[(size_t)NPAIRS * HIDDEN];
__device__ float g_hs[(size_t)PBMAX * 128 * HIDDEN];    // gathered A, tiled [pb][kk64][16KB]
__device__ float g_wtg[WSZ];   // gate^T tiled [e][nb6][kk64][16KB]
__device__ float g_wtu[WSZ];
__device__ float g_wtd[WSZ];   // down^T tiled [e][nb16][kk24][16KB]

__device__ __forceinline__ uint32_t smem_u32(const void* p) {
    return (uint32_t)__cvta_generic_to_shared(p);
}
__device__ __forceinline__ float f2tf(float x) {
    uint32_t r;
    asm("cvt.rna.tf32.f32 %0, %1;" : "=r"(r) : "f"(x));
    return __uint_as_float(r);
}
#define SW128(o) ((o) ^ (((o) >> 3) & 0x70))
#define MBAR_INIT(mb, c) asm volatile("mbarrier.init.shared.b64 [%0], %1;" :: "r"(mb), "r"(c) : "memory")
#define MBAR_ARRIVE_TX(mb, tx) asm volatile("mbarrier.arrive.expect_tx.shared.b64 _, [%0], %1;" :: "r"(mb), "r"(tx) : "memory")
#define BULK_G2S(dst, src, sz, mb)                                            \
    asm volatile("cp.async.bulk.shared::cluster.global.mbarrier::complete_tx::bytes [%0], [%1], %2, [%3];" \
                 :: "r"(dst), "l"(src), "r"(sz), "r"(mb) : "memory")
#define MBAR_WAIT(mb, ph)                                                     \
    asm volatile("{\n\t.reg .pred P1;\n\t"                                    \
        "WL_%=:\n\t"                                                          \
        "mbarrier.try_wait.parity.acquire.cta.shared::cta.b64 P1, [%0], %1, 0x989680;\n\t" \
        "@P1 bra.uni WD_%=;\n\t"                                              \
        "bra.uni WL_%=;\n\t"                                                  \
        "WD_%=:\n\t}" :: "r"(mb), "r"(ph) : "memory")

#if defined(__CUDA_ARCH_FEAT_SM103_ALL) || defined(__CUDA_ARCH_FEAT_SM100_ALL) || defined(__CUDA_ARCH_FEAT_SM101_ALL)
#define TC_OK 1
#endif

#ifdef TC_OK
#define TC_ALLOC(sm, n)  asm volatile("tcgen05.alloc.cta_group::1.sync.aligned.shared::cta.b32 [%0], %1;" :: "r"(sm), "r"(n) : "memory")
#define TC_DEALLOC(t, n) asm volatile("tcgen05.dealloc.cta_group::1.sync.aligned.b32 %0, %1;" :: "r"(t), "r"(n))
#define TC_RELINQ()      asm volatile("tcgen05.relinquish_alloc_permit.cta_group::1.sync.aligned;")
#define TC_COMMIT(mb)    asm volatile("tcgen05.commit.cta_group::1.mbarrier::arrive::one.shared::cluster.b64 [%0];" :: "r"(mb) : "memory")
#define TC_FENCE_AFTER() asm volatile("tcgen05.fence::after_thread_sync;" ::: "memory")
#define TC_WAIT_LD()     asm volatile("tcgen05.wait::ld.sync.aligned;" ::: "memory")
#define FENCE_ASYNC()    asm volatile("fence.proxy.async.shared::cta;" ::: "memory")
#define LDTM_X32(r, a)                                                        \
    asm volatile("tcgen05.ld.sync.aligned.32x32b.x32.b32 "                    \
        "{%0,%1,%2,%3,%4,%5,%6,%7,%8,%9,%10,%11,%12,%13,%14,%15,"             \
        "%16,%17,%18,%19,%20,%21,%22,%23,%24,%25,%26,%27,%28,%29,%30,%31},[%32];" \
        : "=r"((r)[0]),"=r"((r)[1]),"=r"((r)[2]),"=r"((r)[3]),                \
          "=r"((r)[4]),"=r"((r)[5]),"=r"((r)[6]),"=r"((r)[7]),                \
          "=r"((r)[8]),"=r"((r)[9]),"=r"((r)[10]),"=r"((r)[11]),              \
          "=r"((r)[12]),"=r"((r)[13]),"=r"((r)[14]),"=r"((r)[15]),            \
          "=r"((r)[16]),"=r"((r)[17]),"=r"((r)[18]),"=r"((r)[19]),            \
          "=r"((r)[20]),"=r"((r)[21]),"=r"((r)[22]),"=r"((r)[23]),            \
          "=r"((r)[24]),"=r"((r)[25]),"=r"((r)[26]),"=r"((r)[27]),            \
          "=r"((r)[28]),"=r"((r)[29]),"=r"((r)[30]),"=r"((r)[31]) : "r"(a))

__device__ __forceinline__ uint64_t desc_k(uint32_t a) {     // SW128 K-major
    return (uint64_t(2) << 61) | (uint64_t(1) << 46) | (uint64_t(64) << 32) |
           (uint64_t(1) << 16) | ((uint64_t)(a >> 4) & 0x3FFF);
}
#define IDESC64 ((1u<<4)|(2u<<7)|(2u<<10)|(8u<<17)|(8u<<24))
__device__ __forceinline__ void mma_n64(uint32_t d, uint64_t ad, uint64_t bd, uint32_t acc) {
    asm volatile(
        "{\n\t.reg .pred p;\n\tsetp.ne.u32 p, %4, 0;\n\t"
        "tcgen05.mma.cta_group::1.kind::tf32 [%0], %1, %2, %3, {%5,%5,%5,%5}, p;\n\t}"
        :: "r"(d), "l"(ad), "l"(bd), "r"(IDESC64), "r"(acc), "r"(0u) : "memory");
}
#endif

// ---------------- tiled-layout helpers ----------------
__device__ __forceinline__ char* act_addr(int ps, int k) {
    size_t tile = (size_t)(ps >> 7) * KT2 + (k >> 5);
    uint32_t inner = SW128((uint32_t)(((ps & 127) << 7) + ((k & 31) << 2)));
    return (char*)g_act + tile * 16384 + inner;
}

// ---------------- prefix kernels ----------------
__global__ void init_kernel() {
    if (threadIdx.x < NEXP) {
        g_counts[threadIdx.x] = 0;
        g_done[threadIdx.x] = 0;
        g_tgu[threadIdx.x] = 0;
        g_td[threadIdx.x] = 0;
        g_gat[threadIdx.x] = 0;
    }
}
__global__ void route_kernel(const float* __restrict__ logits) {
    int t = blockIdx.x * blockDim.x + threadIdx.x;
    if (t >= TOKENS) return;
    float l[NEXP];
    const float* lp = logits + (size_t)t * NEXP;
#pragma unroll
    for (int i = 0; i < NEXP; ++i) l[i] = lp[i];
    float val[TOPK]; int sel[TOPK];
#pragma unroll
    for (int k = 0; k < TOPK; ++k) {
        float best = -1e30f; int bi = 0;
#pragma unroll
        for (int i = 0; i < NEXP; ++i)
            if (l[i] > best) { best = l[i]; bi = i; }
        val[k] = best; sel[k] = bi; l[bi] = -1e30f;
    }
    float m = val[0], s = 0.f, w[TOPK];
#pragma unroll
    for (int k = 0; k < TOPK; ++k) { w[k] = __expf(val[k] - m); s += w[k]; }
    float inv = 1.f / s;
#pragma unroll
    for (int k = 0; k < TOPK; ++k) {
        g_pair_e[t * TOPK + k] = sel[k];
        g_pair_w[t * TOPK + k] = w[k] * inv;
        atomicAdd(&g_counts[sel[k]], 1);
    }
}
__global__ void scan_kernel() {
    if (threadIdx.x == 0) {
        int acc = 0, pacc = 0;
        for (int e = 0; e < NEXP; ++e) {
            g_offsets[e] = acc; g_cursor[e] = acc;
            g_poff[e] = pacc;
            acc += g_counts[e];
            pacc += (g_counts[e] + 127) & ~127;
        }
        g_offsets[NEXP] = acc;
        g_poff[NEXP] = pacc;
    }
}
__global__ void scatter_kernel() {
    int p = blockIdx.x * blockDim.x + threadIdx.x;
    if (p >= NPAIRS) return;
    int slot = atomicAdd(&g_cursor[g_pair_e[p]], 1);
    g_row_token[slot]  = p >> 3;
    g_row_weight[slot] = g_pair_w[p];
    g_s2p[slot] = p;
}

// ==== mega kernel: gather | tiles | gemm1 | gemm2, dataflow-gated ====
__global__ void __launch_bounds__(256, 2)
mega_kernel(const float* __restrict__ hidden,
            const float* __restrict__ gate_w,
            const float* __restrict__ up_w,
            const float* __restrict__ down_w) {
#ifdef TC_OK
    int bid = blockIdx.x;
    int tid = threadIdx.x, wid = tid >> 5, lane = tid & 31;

    extern __shared__ char dyn[];
    uint32_t sbase = (smem_u32(dyn) + 1023u) & ~1023u;
    __shared__ uint32_t s_tmem[1];
    __shared__ __align__(8) uint64_t s_full[2], s_mdone[2], s_fin[1];
    __shared__ float t[32][33];

    if (bid < BID_TILE) {
        // ---------------- gather (expert rows -> g_hs tiled) ----------------
        int pb = bid / KT1, kk = bid % KT1;
        __shared__ int s_e;
        if (tid == 0) {
            int e = 0;
            while (e < NEXP && !(g_poff[e] <= pb * 128 && pb * 128 < g_poff[e + 1])) ++e;
            s_e = e;
        }
        __syncthreads();
        int e = s_e;
        if (e >= NEXP) return;
        int off = g_offsets[e], cnt = g_counts[e];
        char* tile = (char*)g_hs + ((size_t)pb * KT1 + kk) * 16384;
#pragma unroll
        for (int j = 0; j < 4; ++j) {
            int f = tid + j * 256;
            int row = f >> 3, c = f & 7;
            int lidx = pb * 128 + row - g_poff[e];
            if (lidx > cnt - 1) lidx = cnt - 1;
            int token = g_row_token[off + lidx];
            float4 v = *(const float4*)(hidden + (size_t)token * HIDDEN + kk * 32 + c * 4);
            v.x = f2tf(v.x); v.y = f2tf(v.y); v.z = f2tf(v.z); v.w = f2tf(v.w);
            *(float4*)(tile + SW128((uint32_t)(row * 128 + c * 16))) = v;
        }
        __syncthreads();
        if (tid == 0) { __threadfence(); atomicAdd(&g_gat[e], 1); }
    } else if (bid < BID_G1) {
        // ---------------- weight tiling, expert-major ----------------
        int tb = bid - BID_TILE;
        int e = tb / TPEREX;
        int w = tb % TPEREX;
        int which = w / 768;          // 0=gate, 1=up, 2=down
        int idx = w % 768;
        const float* src; float* dst; int K, N, NB, KK, kb, nbk;
        if (which < 2) {
            src = which ? up_w : gate_w;
            dst = which ? g_wtu : g_wtg;
            K = HIDDEN; N = INTER; NB = 6; KK = KT1;
            kb = idx / 24; nbk = idx % 24;
        } else {
            src = down_w; dst = g_wtd;
            K = INTER; N = HIDDEN; NB = 16; KK = KT2;
            kb = idx / 64; nbk = idx % 64;
        }
        int k0 = kb * 64, n0 = nbk * 32;
        int r = tid >> 3, c4 = (tid & 7) << 2;
        int n = n0 + r;
#pragma unroll
        for (int h = 0; h < 2; ++h) {
            int kk0 = k0 + h * 32;
            float4 v = *(const float4*)(src + ((size_t)e * K + kk0 + r) * N + n0 + c4);
            t[r][c4] = v.x; t[r][c4 + 1] = v.y; t[r][c4 + 2] = v.z; t[r][c4 + 3] = v.w;
            __syncthreads();
            size_t tile = ((size_t)e * NB + (n >> 7)) * KK + (kk0 >> 5);
            uint32_t inner = SW128((uint32_t)(((n & 127) << 7) + (c4 << 2)));
            float4 o;
            o.x = f2tf(t[c4    ][r]);
            o.y = f2tf(t[c4 + 1][r]);
            o.z = f2tf(t[c4 + 2][r]);
            o.w = f2tf(t[c4 + 3][r]);
            *(float4*)((char*)dst + tile * 16384 + inner) = o;
            __syncthreads();
        }
        if (tid == 0) {
            __threadfence();
            atomicAdd(which < 2 ? &g_tgu[e] : &g_td[e], 1);
        }
    } else if (bid < BID_G2) {
        // ---------------- GEMM1: gate+up, swiglu -> g_act ----------------
        int b1 = bid - BID_G1;
        int e  = b1 / G1CNT;
        int r  = b1 % G1CNT;
        int mb = r / 6, nb = r % 6;

        // acquire: expert's gather + gate/up tiles done
        if (tid == 0) {
            int need = ((g_poff[e + 1] - g_poff[e]) >> 7) * KT1;
            while (*(volatile int*)&g_tgu[e] < 1536) __nanosleep(100);
            while (*(volatile int*)&g_gat[e] < need) __nanosleep(100);
            __threadfence();
        }
        __syncthreads();

        int off = g_offsets[e], cnt = g_offsets[e + 1] - off;
        int m0 = mb * 128;
        if (m0 >= cnt) {
            __syncthreads();
            if (tid == 0) atomicAdd(&g_done[e], 1);
            return;
        }
        int n0 = nb * 128;

        if (wid == 0) { TC_ALLOC(smem_u32(s_tmem), 256); TC_RELINQ(); }
        if (tid == 0) {
#pragma unroll
            for (int i = 0; i < 2; ++i) {
                MBAR_INIT(smem_u32(&s_full[i]), 1);
                MBAR_INIT(smem_u32(&s_mdone[i]), 1);
            }
            MBAR_INIT(smem_u32(s_fin), 1);
        }
        __syncthreads();
        uint32_t tmem = s_tmem[0];
        int pb = (g_poff[e] + m0) >> 7;

        if (tid == 32) {   // producer warp
            uint32_t full[2]  = { smem_u32(&s_full[0]),  smem_u32(&s_full[1])  };
            uint32_t mdone[2] = { smem_u32(&s_mdone[0]), smem_u32(&s_mdone[1]) };
            const char* a0 = (const char*)g_hs + ((size_t)pb * KT1) * 16384;
            const char* tg = (const char*)g_wtg + (((size_t)e * 6 + nb) * KT1) * 16384;
            const char* tu = (const char*)g_wtu + (((size_t)e * 6 + nb) * KT1) * 16384;
            for (int kt = 0; kt < KT1; ++kt) {
                int s = kt & 1;
                if (kt >= 2) MBAR_WAIT(mdone[s], (kt / 2 - 1) & 1);
                MBAR_ARRIVE_TX(full[s], 49152u);
                uint32_t sb = sbase + s * STG;
                BULK_G2S(sb,           a0 + (size_t)kt * 16384, 16384u, full[s]);
                BULK_G2S(sb + 16384u,  tg + (size_t)kt * 16384, 16384u, full[s]);
                BULK_G2S(sb + 32768u,  tu + (size_t)kt * 16384, 16384u, full[s]);
            }
        }
        if (tid == 0) {    // consumer
            uint32_t full[2]  = { smem_u32(&s_full[0]),  smem_u32(&s_full[1])  };
            uint32_t mdone[2] = { smem_u32(&s_mdone[0]), smem_u32(&s_mdone[1]) };
            for (int kt = 0; kt < KT1; ++kt) {
                int s = kt & 1;
                MBAR_WAIT(full[s], (kt / 2) & 1);
                FENCE_ASYNC();
                uint32_t sb = sbase + s * STG;
                uint64_t ad = desc_k(sb);
                uint64_t bg = desc_k(sb + 16384u), bu = desc_k(sb + 32768u);
#pragma unroll
                for (int ks = 0; ks < 4; ++ks) {
                    uint32_t acc = (kt > 0 || ks > 0) ? 1u : 0u;
#pragma unroll
                    for (int j = 0; j < 2; ++j) {
                        mma_n64(tmem + j * 64,       ad + ks * 2, bg + j * 512 + ks * 2, acc);
                        mma_n64(tmem + 128 + j * 64, ad + ks * 2, bu + j * 512 + ks * 2, acc);
                    }
                }
                TC_COMMIT(mdone[s]);
            }
            TC_COMMIT(smem_u32(s_fin));
            MBAR_WAIT(smem_u32(s_fin), 0);
        }
        __syncthreads();
        TC_FENCE_AFTER();

        int sp = wid & 3, ch = wid >> 2;
        int row = sp * 32 + lane;
        bool valid = (m0 + row) < cnt;
        int ps = g_poff[e] + m0 + row;
        size_t tb0 = (size_t)(ps >> 7) * KT2 * 16384;
        uint32_t rinner = (uint32_t)((ps & 127) << 7);
        uint32_t tmem2 = s_tmem[0];
#pragma unroll
        for (int cb = 0; cb < 2; ++cb) {
            int c0 = ch * 64 + cb * 32;
            uint32_t rg[32], ru[32];
            LDTM_X32(rg, tmem2 + c0);
            LDTM_X32(ru, tmem2 + 128 + c0);
            TC_WAIT_LD();
            if (valid) {
                char* tile = (char*)g_act + tb0 + (size_t)((n0 + c0) >> 5) * 16384;
#pragma unroll
                for (int i = 0; i < 32; i += 4) {
                    float4 v;
#pragma unroll
                    for (int q = 0; q < 4; ++q) {
                        float g = __uint_as_float(rg[i + q]);
                        float u = __uint_as_float(ru[i + q]);
                        ((float*)&v)[q] = f2tf(g / (1.f + __expf(-g)) * u);
                    }
                    *(float4*)(tile + SW128(rinner + i * 4)) = v;
                }
            }
        }
        __syncthreads();
        if (wid == 0) TC_DEALLOC(tmem2, 256);
        __syncthreads();
        if (tid == 0) { __threadfence(); atomicAdd(&g_done[e], 1); }
    } else {
        // ---------------- GEMM2: down-proj -> g_pout ----------------
        int b2 = bid - BID_G2;
        int e  = b2 / G2CNT;
        int r  = b2 % G2CNT;
        int mb = r / 8, nbp = r % 8;

        // acquire: expert's gemm1 + down tiles done
        if (tid == 0) {
            while (*(volatile int*)&g_td[e] < 768) __nanosleep(100);
            while (*(volatile int*)&g_done[e] < G1CNT) __nanosleep(200);
            __threadfence();
        }
        __syncthreads();

        int off = g_offsets[e], cnt = g_offsets[e + 1] - off;
        int m0 = mb * 128;
        if (m0 >= cnt) return;
        int nb0 = nbp * 2;
        int n0 = nb0 * 128;

        if (wid == 0) { TC_ALLOC(smem_u32(s_tmem), 256); TC_RELINQ(); }
        if (tid == 0) {
#pragma unroll
            for (int i = 0; i < 2; ++i) {
                MBAR_INIT(smem_u32(&s_full[i]), 1);
                MBAR_INIT(smem_u32(&s_mdone[i]), 1);
            }
            MBAR_INIT(smem_u32(s_fin), 1);
        }
        __syncthreads();
        uint32_t tmem = s_tmem[0];
        int pb = (g_poff[e] + m0) >> 7;

        if (tid == 32) {   // producer
            uint32_t full[2]  = { smem_u32(&s_full[0]),  smem_u32(&s_full[1])  };
            uint32_t mdone[2] = { smem_u32(&s_mdone[0]), smem_u32(&s_mdone[1]) };
            const char* a0 = (const char*)g_act + ((size_t)pb * KT2) * 16384;
            const char* b0p = (const char*)g_wtd + (((size_t)e * 16 + nb0)     * KT2) * 16384;
            const char* b1p = (const char*)g_wtd + (((size_t)e * 16 + nb0 + 1) * KT2) * 16384;
            for (int kt = 0; kt < KT2; ++kt) {
                int s = kt & 1;
                if (kt >= 2) MBAR_WAIT(mdone[s], (kt / 2 - 1) & 1);
                MBAR_ARRIVE_TX(full[s], 49152u);
                uint32_t sb = sbase + s * STG;
                BULK_G2S(sb,          a0  + (size_t)kt * 16384, 16384u, full[s]);
                BULK_G2S(sb + 16384u, b0p + (size_t)kt * 16384, 16384u, full[s]);
                BULK_G2S(sb + 32768u, b1p + (size_t)kt * 16384, 16384u, full[s]);
            }
        }
        if (tid == 0) {    // consumer
            uint32_t full[2]  = { smem_u32(&s_full[0]),  smem_u32(&s_full[1])  };
            uint32_t mdone[2] = { smem_u32(&s_mdone[0]), smem_u32(&s_mdone[1]) };
            for (int kt = 0; kt < KT2; ++kt) {
                int s = kt & 1;
                MBAR_WAIT(full[s], (kt / 2) & 1);
                FENCE_ASYNC();
                uint32_t sb = sbase + s * STG;
                uint64_t ad = desc_k(sb);
                uint64_t b0 = desc_k(sb + 16384u), b1 = desc_k(sb + 32768u);
#pragma unroll
                for (int ks = 0; ks < 4; ++ks) {
                    uint32_t acc = (kt > 0 || ks > 0) ? 1u : 0u;
#pragma unroll
                    for (int j = 0; j < 4; ++j) {
                        uint64_t bd = (j < 2) ? (b0 + j * 512 + ks * 2)
                                              : (b1 + (j - 2) * 512 + ks * 2);
                        mma_n64(tmem + j * 64, ad + ks * 2, bd, acc);
                    }
                }
                TC_COMMIT(mdone[s]);
            }
            TC_COMMIT(smem_u32(s_fin));
            MBAR_WAIT(smem_u32(s_fin), 0);
        }
        __syncthreads();
        TC_FENCE_AFTER();

        int sp = wid & 3, ch = wid >> 2;
        int row = sp * 32 + lane;
        bool valid = (m0 + row) < cnt;
        int slot = off + m0 + row; if (slot > NPAIRS - 1) slot = NPAIRS - 1;
        float w = g_row_weight[slot];
        float* dst = g_pout + (size_t)g_s2p[slot] * HIDDEN + n0;
        uint32_t tmem2 = s_tmem[0];
#pragma unroll
        for (int cb = 0; cb < 4; ++cb) {
            int c0 = ch * 128 + cb * 32;
            uint32_t rr[32];
            LDTM_X32(rr, tmem2 + c0);
            TC_WAIT_LD();
            if (valid) {
#pragma unroll
                for (int i = 0; i < 32; i += 4) {
                    float4 v;
                    ((float*)&v)[0] = __uint_as_float(rr[i])     * w;
                    ((float*)&v)[1] = __uint_as_float(rr[i + 1]) * w;
                    ((float*)&v)[2] = __uint_as_float(rr[i + 2]) * w;
                    ((float*)&v)[3] = __uint_as_float(rr[i + 3]) * w;
                    *(float4*)(dst + c0 + i) = v;
                }
            }
        }
        __syncthreads();
        if (wid == 0) TC_DEALLOC(tmem2, 256);
    }
#endif
}

// ---------------- combine ----------------
__global__ void combine_kernel(float* __restrict__ out) {
    int t = blockIdx.x, c = threadIdx.x;
    const float* base = g_pout + (size_t)t * TOPK * HIDDEN + c * 4;
    float4 acc = make_float4(0.f, 0.f, 0.f, 0.f);
#pragma unroll
    for (int k = 0; k < TOPK; ++k) {
        float4 v = *(const float4*)(base + (size_t)k * HIDDEN);
        acc.x += v.x; acc.y += v.y; acc.z += v.z; acc.w += v.w;
    }
    *(float4*)(out + (size_t)t * HIDDEN + c * 4) = acc;
}

// ---------------- launch ----------------
extern "C" void kernel_launch(void* const* d_in, const int* in_sizes, int n_in,
                              void* d_out, int out_size) {
    const float* hidden = (const float*)d_in[0];
    const float* logits = (const float*)d_in[1];
    const float* gate   = (const float*)d_in[2];
    const float* up     = (const float*)d_in[3];
    const float* down   = (const float*)d_in[4];
    float* out = (float*)d_out;

    static int inited = 0;
    if (!inited) {
        cudaFuncSetAttribute(mega_kernel, cudaFuncAttributeMaxDynamicSharedMemorySize, 2 * STG + 1024);
        inited = 1;
    }

    init_kernel     <<<1, 64>>>();
    route_kernel    <<<TOKENS / 256, 256>>>(logits);
    scan_kernel     <<<1, 32>>>();
    scatter_kernel  <<<NPAIRS / 256, 256>>>();
    mega_kernel     <<<NBIDS, 256, 2 * STG + 1024>>>(hidden, gate, up, down);
    combine_kernel  <<<TOKENS, 512>>>(out);
}

// round 17
// speedup vs baseline: 2.9137x; 2.9137x over previous
#include <cuda_runtime.h>
#include <cstdint>

#define TOKENS 4096
#define HIDDEN 2048
#define INTER  768
#define NEXP   64
#define TOPK   8
#define NPAIRS (TOKENS*TOPK)
#define BK     32
#define STG    49152        // stage: A 16KB + B 2x16KB
#define KT1    (HIDDEN/BK)  // 64
#define KT2    (INTER/BK)   // 24
#define WSZ    100663296
#define PBMAX  320
#define G1CNT  (16*6)
#define G1TOT  (G1CNT*NEXP) // 6144
#define G2CNT  (16*8)       // 128 per expert
#define G2TOT  (G2CNT*NEXP) // 8192
#define BID_G2 G1TOT
#define BID_CB (G1TOT+G2TOT)
#define NBIDS  (BID_CB+TOKENS)

__device__ int   g_done[NEXP];
__device__ int   g_done2[NEXP];
__device__ int   g_counts[NEXP];
__device__ int   g_offsets[NEXP+1];
__device__ int   g_poff[NEXP+1];
__device__ int   g_cursor[NEXP];
__device__ int   g_pair_e[NPAIRS];
__device__ float g_pair_w[NPAIRS];
__device__ int   g_row_token[NPAIRS];
__device__ float g_row_weight[NPAIRS];
__device__ int   g_s2p[NPAIRS];
__device__ float g_act[(size_t)PBMAX * 128 * INTER];    // tiled [pb][kk24][16KB]
__device__ float g_pout[(size_t)NPAIRS * HIDDEN];
__device__ float g_hs[(size_t)PBMAX * 128 * HIDDEN];    // gathered A, tiled [pb][kk64][16KB]
__device__ float g_wtg[WSZ];   // gate^T tiled [e][nb6][kk64][16KB]
__device__ float g_wtu[WSZ];
__device__ float g_wtd[WSZ];   // down^T tiled [e][nb16][kk24][16KB]

__device__ __forceinline__ uint32_t smem_u32(const void* p) {
    return (uint32_t)__cvta_generic_to_shared(p);
}
__device__ __forceinline__ float f2tf(float x) {
    uint32_t r;
    asm("cvt.rna.tf32.f32 %0, %1;" : "=r"(r) : "f"(x));
    return __uint_as_float(r);
}
#define SW128(o) ((o) ^ (((o) >> 3) & 0x70))
#define MBAR_INIT(mb, c) asm volatile("mbarrier.init.shared.b64 [%0], %1;" :: "r"(mb), "r"(c) : "memory")
#define MBAR_ARRIVE_TX(mb, tx) asm volatile("mbarrier.arrive.expect_tx.shared.b64 _, [%0], %1;" :: "r"(mb), "r"(tx) : "memory")
#define BULK_G2S(dst, src, sz, mb)                                            \
    asm volatile("cp.async.bulk.shared::cluster.global.mbarrier::complete_tx::bytes [%0], [%1], %2, [%3];" \
                 :: "r"(dst), "l"(src), "r"(sz), "r"(mb) : "memory")
#define MBAR_WAIT(mb, ph)                                                     \
    asm volatile("{\n\t.reg .pred P1;\n\t"                                    \
        "WL_%=:\n\t"                                                          \
        "mbarrier.try_wait.parity.acquire.cta.shared::cta.b64 P1, [%0], %1, 0x989680;\n\t" \
        "@P1 bra.uni WD_%=;\n\t"                                              \
        "bra.uni WL_%=;\n\t"                                                  \
        "WD_%=:\n\t}" :: "r"(mb), "r"(ph) : "memory")

#if defined(__CUDA_ARCH_FEAT_SM103_ALL) || defined(__CUDA_ARCH_FEAT_SM100_ALL) || defined(__CUDA_ARCH_FEAT_SM101_ALL)
#define TC_OK 1
#endif

#ifdef TC_OK
#define TC_ALLOC(sm, n)  asm volatile("tcgen05.alloc.cta_group::1.sync.aligned.shared::cta.b32 [%0], %1;" :: "r"(sm), "r"(n) : "memory")
#define TC_DEALLOC(t, n) asm volatile("tcgen05.dealloc.cta_group::1.sync.aligned.b32 %0, %1;" :: "r"(t), "r"(n))
#define TC_RELINQ()      asm volatile("tcgen05.relinquish_alloc_permit.cta_group::1.sync.aligned;")
#define TC_COMMIT(mb)    asm volatile("tcgen05.commit.cta_group::1.mbarrier::arrive::one.shared::cluster.b64 [%0];" :: "r"(mb) : "memory")
#define TC_FENCE_AFTER() asm volatile("tcgen05.fence::after_thread_sync;" ::: "memory")
#define TC_WAIT_LD()     asm volatile("tcgen05.wait::ld.sync.aligned;" ::: "memory")
#define FENCE_ASYNC()    asm volatile("fence.proxy.async.shared::cta;" ::: "memory")
#define LDTM_X32(r, a)                                                        \
    asm volatile("tcgen05.ld.sync.aligned.32x32b.x32.b32 "                    \
        "{%0,%1,%2,%3,%4,%5,%6,%7,%8,%9,%10,%11,%12,%13,%14,%15,"             \
        "%16,%17,%18,%19,%20,%21,%22,%23,%24,%25,%26,%27,%28,%29,%30,%31},[%32];" \
        : "=r"((r)[0]),"=r"((r)[1]),"=r"((r)[2]),"=r"((r)[3]),                \
          "=r"((r)[4]),"=r"((r)[5]),"=r"((r)[6]),"=r"((r)[7]),                \
          "=r"((r)[8]),"=r"((r)[9]),"=r"((r)[10]),"=r"((r)[11]),              \
          "=r"((r)[12]),"=r"((r)[13]),"=r"((r)[14]),"=r"((r)[15]),            \
          "=r"((r)[16]),"=r"((r)[17]),"=r"((r)[18]),"=r"((r)[19]),            \
          "=r"((r)[20]),"=r"((r)[21]),"=r"((r)[22]),"=r"((r)[23]),            \
          "=r"((r)[24]),"=r"((r)[25]),"=r"((r)[26]),"=r"((r)[27]),            \
          "=r"((r)[28]),"=r"((r)[29]),"=r"((r)[30]),"=r"((r)[31]) : "r"(a))

__device__ __forceinline__ uint64_t desc_k(uint32_t a) {     // SW128 K-major
    return (uint64_t(2) << 61) | (uint64_t(1) << 46) | (uint64_t(64) << 32) |
           (uint64_t(1) << 16) | ((uint64_t)(a >> 4) & 0x3FFF);
}
#define IDESC64 ((1u<<4)|(2u<<7)|(2u<<10)|(8u<<17)|(8u<<24))
__device__ __forceinline__ void mma_n64(uint32_t d, uint64_t ad, uint64_t bd, uint32_t acc) {
    asm volatile(
        "{\n\t.reg .pred p;\n\tsetp.ne.u32 p, %4, 0;\n\t"
        "tcgen05.mma.cta_group::1.kind::tf32 [%0], %1, %2, %3, {%5,%5,%5,%5}, p;\n\t}"
        :: "r"(d), "l"(ad), "l"(bd), "r"(IDESC64), "r"(acc), "r"(0u) : "memory");
}
#endif

// ---------------- tiled-layout helpers ----------------
__device__ __forceinline__ char* act_addr(int ps, int k) {
    size_t tile = (size_t)(ps >> 7) * KT2 + (k >> 5);
    uint32_t inner = SW128((uint32_t)(((ps & 127) << 7) + ((k & 31) << 2)));
    return (char*)g_act + tile * 16384 + inner;
}

// ---------------- prep ----------------
// 2 k-subtiles per block (k-span 64)
__global__ void tile_kernel(const float* __restrict__ src, float* __restrict__ dst,
                            int K, int N, int NB, int KK) {
    __shared__ float t[32][33];
    int e = blockIdx.z;
    int k0 = blockIdx.x * 64, n0 = blockIdx.y * 32;
    int r = threadIdx.x >> 3, c4 = (threadIdx.x & 7) << 2;
    int n = n0 + r;
#pragma unroll
    for (int h = 0; h < 2; ++h) {
        int kk0 = k0 + h * 32;
        float4 v = *(const float4*)(src + ((size_t)e * K + kk0 + r) * N + n0 + c4);
        t[r][c4] = v.x; t[r][c4 + 1] = v.y; t[r][c4 + 2] = v.z; t[r][c4 + 3] = v.w;
        __syncthreads();
        size_t tile = ((size_t)e * NB + (n >> 7)) * KK + (kk0 >> 5);
        uint32_t inner = SW128((uint32_t)(((n & 127) << 7) + (c4 << 2)));
        float4 o;
        o.x = f2tf(t[c4    ][r]);
        o.y = f2tf(t[c4 + 1][r]);
        o.z = f2tf(t[c4 + 2][r]);
        o.w = f2tf(t[c4 + 3][r]);
        *(float4*)((char*)dst + tile * 16384 + inner) = o;
        __syncthreads();
    }
}
__global__ void init_kernel() {
    if (threadIdx.x < NEXP) {
        g_counts[threadIdx.x] = 0;
        g_done[threadIdx.x] = 0;
        g_done2[threadIdx.x] = 0;
    }
}

__global__ void route_kernel(const float* __restrict__ logits) {
    int t = blockIdx.x * blockDim.x + threadIdx.x;
    if (t >= TOKENS) return;
    float l[NEXP];
    const float* lp = logits + (size_t)t * NEXP;
#pragma unroll
    for (int i = 0; i < NEXP; ++i) l[i] = lp[i];
    float val[TOPK]; int sel[TOPK];
#pragma unroll
    for (int k = 0; k < TOPK; ++k) {
        float best = -1e30f; int bi = 0;
#pragma unroll
        for (int i = 0; i < NEXP; ++i)
            if (l[i] > best) { best = l[i]; bi = i; }
        val[k] = best; sel[k] = bi; l[bi] = -1e30f;
    }
    float m = val[0], s = 0.f, w[TOPK];
#pragma unroll
    for (int k = 0; k < TOPK; ++k) { w[k] = __expf(val[k] - m); s += w[k]; }
    float inv = 1.f / s;
#pragma unroll
    for (int k = 0; k < TOPK; ++k) {
        g_pair_e[t * TOPK + k] = sel[k];
        g_pair_w[t * TOPK + k] = w[k] * inv;
        atomicAdd(&g_counts[sel[k]], 1);
    }
}
__global__ void scan_kernel() {
    if (threadIdx.x == 0) {
        int acc = 0, pacc = 0;
        for (int e = 0; e < NEXP; ++e) {
            g_offsets[e] = acc; g_cursor[e] = acc;
            g_poff[e] = pacc;
            acc += g_counts[e];
            pacc += (g_counts[e] + 127) & ~127;
        }
        g_offsets[NEXP] = acc;
        g_poff[NEXP] = pacc;
    }
}
__global__ void scatter_kernel() {
    int p = blockIdx.x * blockDim.x + threadIdx.x;
    if (p >= NPAIRS) return;
    int slot = atomicAdd(&g_cursor[g_pair_e[p]], 1);
    g_row_token[slot]  = p >> 3;
    g_row_weight[slot] = g_pair_w[p];
    g_s2p[slot] = p;
}
__global__ void gather_kernel(const float* __restrict__ hidden) {
    int pb = blockIdx.x, kk = blockIdx.y;
    __shared__ int s_e;
    if (threadIdx.x == 0) {
        int e = 0;
        while (e < NEXP && !(g_poff[e] <= pb * 128 && pb * 128 < g_poff[e + 1])) ++e;
        s_e = e;
    }
    __syncthreads();
    int e = s_e;
    if (e >= NEXP) return;
    int off = g_offsets[e], cnt = g_counts[e];
    char* tile = (char*)g_hs + ((size_t)pb * KT1 + kk) * 16384;
#pragma unroll
    for (int j = 0; j < 4; ++j) {
        int f = threadIdx.x + j * 256;
        int row = f >> 3, c = f & 7;
        int lidx = pb * 128 + row - g_poff[e];
        if (lidx > cnt - 1) lidx = cnt - 1;
        int token = g_row_token[off + lidx];
        float4 v = *(const float4*)(hidden + (size_t)token * HIDDEN + kk * 32 + c * 4);
        v.x = f2tf(v.x); v.y = f2tf(v.y); v.z = f2tf(v.z); v.w = f2tf(v.w);
        *(float4*)(tile + SW128((uint32_t)(row * 128 + c * 16))) = v;
    }
}

// ==== fused tcgen05 GEMM1 | GEMM2 | combine, dataflow-gated ====
__global__ void __launch_bounds__(256, 2)
gemm_fused(float* __restrict__ out) {
#ifdef TC_OK
    int bid = blockIdx.x;
    int tid = threadIdx.x, wid = tid >> 5, lane = tid & 31;

    extern __shared__ char dyn[];
    uint32_t sbase = (smem_u32(dyn) + 1023u) & ~1023u;
    __shared__ uint32_t s_tmem[1];
    __shared__ __align__(8) uint64_t s_full[2], s_mdone[2], s_fin[1];

    if (bid < G1TOT) {
        // ---------------- GEMM1: gate+up, swiglu -> g_act ----------------
        int e  = bid / G1CNT;
        int r  = bid % G1CNT;
        int mb = r / 6, nb = r % 6;
        int off = g_offsets[e], cnt = g_offsets[e + 1] - off;
        int m0 = mb * 128;
        if (m0 >= cnt) {                       // early-exit: still signal
            if (tid == 0) atomicAdd(&g_done[e], 1);
            return;
        }
        int n0 = nb * 128;

        if (wid == 0) { TC_ALLOC(smem_u32(s_tmem), 256); TC_RELINQ(); }
        if (tid == 0) {
#pragma unroll
            for (int i = 0; i < 2; ++i) {
                MBAR_INIT(smem_u32(&s_full[i]), 1);
                MBAR_INIT(smem_u32(&s_mdone[i]), 1);
            }
            MBAR_INIT(smem_u32(s_fin), 1);
        }
        __syncthreads();
        uint32_t tmem = s_tmem[0];
        int pb = (g_poff[e] + m0) >> 7;

        if (tid == 32) {   // producer warp
            uint32_t full[2]  = { smem_u32(&s_full[0]),  smem_u32(&s_full[1])  };
            uint32_t mdone[2] = { smem_u32(&s_mdone[0]), smem_u32(&s_mdone[1]) };
            const char* a0 = (const char*)g_hs + ((size_t)pb * KT1) * 16384;
            const char* tg = (const char*)g_wtg + (((size_t)e * 6 + nb) * KT1) * 16384;
            const char* tu = (const char*)g_wtu + (((size_t)e * 6 + nb) * KT1) * 16384;
            for (int kt = 0; kt < KT1; ++kt) {
                int s = kt & 1;
                if (kt >= 2) MBAR_WAIT(mdone[s], (kt / 2 - 1) & 1);
                MBAR_ARRIVE_TX(full[s], 49152u);
                uint32_t sb = sbase + s * STG;
                BULK_G2S(sb,           a0 + (size_t)kt * 16384, 16384u, full[s]);
                BULK_G2S(sb + 16384u,  tg + (size_t)kt * 16384, 16384u, full[s]);
                BULK_G2S(sb + 32768u,  tu + (size_t)kt * 16384, 16384u, full[s]);
            }
        }
        if (tid == 0) {    // consumer
            uint32_t full[2]  = { smem_u32(&s_full[0]),  smem_u32(&s_full[1])  };
            uint32_t mdone[2] = { smem_u32(&s_mdone[0]), smem_u32(&s_mdone[1]) };
            for (int kt = 0; kt < KT1; ++kt) {
                int s = kt & 1;
                MBAR_WAIT(full[s], (kt / 2) & 1);
                FENCE_ASYNC();
                uint32_t sb = sbase + s * STG;
                uint64_t ad = desc_k(sb);
                uint64_t bg = desc_k(sb + 16384u), bu = desc_k(sb + 32768u);
#pragma unroll
                for (int ks = 0; ks < 4; ++ks) {
                    uint32_t acc = (kt > 0 || ks > 0) ? 1u : 0u;
#pragma unroll
                    for (int j = 0; j < 2; ++j) {
                        mma_n64(tmem + j * 64,       ad + ks * 2, bg + j * 512 + ks * 2, acc);
                        mma_n64(tmem + 128 + j * 64, ad + ks * 2, bu + j * 512 + ks * 2, acc);
                    }
                }
                TC_COMMIT(mdone[s]);
            }
            TC_COMMIT(smem_u32(s_fin));
            MBAR_WAIT(smem_u32(s_fin), 0);
        }
        __syncthreads();
        TC_FENCE_AFTER();

        int sp = wid & 3, ch = wid >> 2;
        int row = sp * 32 + lane;
        bool valid = (m0 + row) < cnt;
        int ps = g_poff[e] + m0 + row;
        size_t tb0 = (size_t)(ps >> 7) * KT2 * 16384;
        uint32_t rinner = (uint32_t)((ps & 127) << 7);
        uint32_t tmem2 = s_tmem[0];
#pragma unroll
        for (int cb = 0; cb < 2; ++cb) {
            int c0 = ch * 64 + cb * 32;
            uint32_t rg[32], ru[32];
            LDTM_X32(rg, tmem2 + c0);
            LDTM_X32(ru, tmem2 + 128 + c0);
            TC_WAIT_LD();
            if (valid) {
                char* tile = (char*)g_act + tb0 + (size_t)((n0 + c0) >> 5) * 16384;
#pragma unroll
                for (int i = 0; i < 32; i += 4) {
                    float4 v;
#pragma unroll
                    for (int q = 0; q < 4; ++q) {
                        float g = __uint_as_float(rg[i + q]);
                        float u = __uint_as_float(ru[i + q]);
                        ((float*)&v)[q] = f2tf(g / (1.f + __expf(-g)) * u);
                    }
                    *(float4*)(tile + SW128(rinner + i * 4)) = v;
                }
            }
        }
        __syncthreads();
        if (wid == 0) TC_DEALLOC(tmem2, 256);
        __syncthreads();
        if (tid == 0) {                       // release
            __threadfence();
            atomicAdd(&g_done[e], 1);
        }
    } else if (bid < BID_CB) {
        // ---------------- GEMM2: down-proj -> g_pout ----------------
        int b2 = bid - BID_G2;
        int e  = b2 / G2CNT;
        int r  = b2 % G2CNT;
        int mb = r / 8, nbp = r % 8;
        int off = g_offsets[e], cnt = g_offsets[e + 1] - off;
        int m0 = mb * 128;
        if (m0 >= cnt) {                       // early-exit: signal combine gate
            if (tid == 0) atomicAdd(&g_done2[e], 1);
            return;
        }
        int nb0 = nbp * 2;
        int n0 = nb0 * 128;

        // wait for this expert's gemm1 CTAs (acquire)
        if (tid == 0) {
            while (*(volatile int*)&g_done[e] < G1CNT) __nanosleep(200);
            __threadfence();
        }
        __syncthreads();

        if (wid == 0) { TC_ALLOC(smem_u32(s_tmem), 256); TC_RELINQ(); }
        if (tid == 0) {
#pragma unroll
            for (int i = 0; i < 2; ++i) {
                MBAR_INIT(smem_u32(&s_full[i]), 1);
                MBAR_INIT(smem_u32(&s_mdone[i]), 1);
            }
            MBAR_INIT(smem_u32(s_fin), 1);
        }
        __syncthreads();
        uint32_t tmem = s_tmem[0];
        int pb = (g_poff[e] + m0) >> 7;

        if (tid == 32) {   // producer
            uint32_t full[2]  = { smem_u32(&s_full[0]),  smem_u32(&s_full[1])  };
            uint32_t mdone[2] = { smem_u32(&s_mdone[0]), smem_u32(&s_mdone[1]) };
            const char* a0 = (const char*)g_act + ((size_t)pb * KT2) * 16384;
            const char* b0p = (const char*)g_wtd + (((size_t)e * 16 + nb0)     * KT2) * 16384;
            const char* b1p = (const char*)g_wtd + (((size_t)e * 16 + nb0 + 1) * KT2) * 16384;
            for (int kt = 0; kt < KT2; ++kt) {
                int s = kt & 1;
                if (kt >= 2) MBAR_WAIT(mdone[s], (kt / 2 - 1) & 1);
                MBAR_ARRIVE_TX(full[s], 49152u);
                uint32_t sb = sbase + s * STG;
                BULK_G2S(sb,          a0  + (size_t)kt * 16384, 16384u, full[s]);
                BULK_G2S(sb + 16384u, b0p + (size_t)kt * 16384, 16384u, full[s]);
                BULK_G2S(sb + 32768u, b1p + (size_t)kt * 16384, 16384u, full[s]);
            }
        }
        if (tid == 0) {    // consumer
            uint32_t full[2]  = { smem_u32(&s_full[0]),  smem_u32(&s_full[1])  };
            uint32_t mdone[2] = { smem_u32(&s_mdone[0]), smem_u32(&s_mdone[1]) };
            for (int kt = 0; kt < KT2; ++kt) {
                int s = kt & 1;
                MBAR_WAIT(full[s], (kt / 2) & 1);
                FENCE_ASYNC();
                uint32_t sb = sbase + s * STG;
                uint64_t ad = desc_k(sb);
                uint64_t b0 = desc_k(sb + 16384u), b1 = desc_k(sb + 32768u);
#pragma unroll
                for (int ks = 0; ks < 4; ++ks) {
                    uint32_t acc = (kt > 0 || ks > 0) ? 1u : 0u;
#pragma unroll
                    for (int j = 0; j < 4; ++j) {
                        uint64_t bd = (j < 2) ? (b0 + j * 512 + ks * 2)
                                              : (b1 + (j - 2) * 512 + ks * 2);
                        mma_n64(tmem + j * 64, ad + ks * 2, bd, acc);
                    }
                }
                TC_COMMIT(mdone[s]);
            }
            TC_COMMIT(smem_u32(s_fin));
            MBAR_WAIT(smem_u32(s_fin), 0);
        }
        __syncthreads();
        TC_FENCE_AFTER();

        int sp = wid & 3, ch = wid >> 2;
        int row = sp * 32 + lane;
        bool valid = (m0 + row) < cnt;
        int slot = off + m0 + row; if (slot > NPAIRS - 1) slot = NPAIRS - 1;
        float w = g_row_weight[slot];
        float* dst = g_pout + (size_t)g_s2p[slot] * HIDDEN + n0;
        uint32_t tmem2 = s_tmem[0];
#pragma unroll
        for (int cb = 0; cb < 4; ++cb) {
            int c0 = ch * 128 + cb * 32;
            uint32_t rr[32];
            LDTM_X32(rr, tmem2 + c0);
            TC_WAIT_LD();
            if (valid) {
#pragma unroll
                for (int i = 0; i < 32; i += 4) {
                    float4 v;
                    ((float*)&v)[0] = __uint_as_float(rr[i])     * w;
                    ((float*)&v)[1] = __uint_as_float(rr[i + 1]) * w;
                    ((float*)&v)[2] = __uint_as_float(rr[i + 2]) * w;
                    ((float*)&v)[3] = __uint_as_float(rr[i + 3]) * w;
                    *(float4*)(dst + c0 + i) = v;
                }
            }
        }
        __syncthreads();
        if (wid == 0) TC_DEALLOC(tmem2, 256);
        __syncthreads();
        if (tid == 0) {                       // release for combine
            __threadfence();
            atomicAdd(&g_done2[e], 1);
        }
    } else {
        // ---------------- combine: sum 8 weighted rows per token ----------
        int t = bid - BID_CB;
        if (tid == 0) {
#pragma unroll
            for (int k = 0; k < TOPK; ++k) {
                int e = g_pair_e[t * TOPK + k];
                while (*(volatile int*)&g_done2[e] < G2CNT) __nanosleep(200);
            }
            __threadfence();
        }
        __syncthreads();
        int c = tid;                      // 256 threads x 8 floats = 2048
        const float* base = g_pout + (size_t)t * TOPK * HIDDEN + c * 8;
        float4 a0 = make_float4(0.f, 0.f, 0.f, 0.f);
        float4 a1 = make_float4(0.f, 0.f, 0.f, 0.f);
#pragma unroll
        for (int k = 0; k < TOPK; ++k) {
            float4 v0 = *(const float4*)(base + (size_t)k * HIDDEN);
            float4 v1 = *(const float4*)(base + (size_t)k * HIDDEN + 4);
            a0.x += v0.x; a0.y += v0.y; a0.z += v0.z; a0.w += v0.w;
            a1.x += v1.x; a1.y += v1.y; a1.z += v1.z; a1.w += v1.w;
        }
        *(float4*)(out + (size_t)t * HIDDEN + c * 8)     = a0;
        *(float4*)(out + (size_t)t * HIDDEN + c * 8 + 4) = a1;
    }
#endif
}

// ---------------- launch ----------------
extern "C" void kernel_launch(void* const* d_in, const int* in_sizes, int n_in,
                              void* d_out, int out_size) {
    const float* hidden = (const float*)d_in[0];
    const float* logits = (const float*)d_in[1];
    const float* gate   = (const float*)d_in[2];
    const float* up     = (const float*)d_in[3];
    const float* down   = (const float*)d_in[4];
    float* out = (float*)d_out;

    static cudaStream_t s2 = nullptr, s3 = nullptr;
    static cudaEvent_t evF = nullptr, evJ1 = nullptr, evJ3 = nullptr;
    if (s2 == nullptr) {   // first (non-captured) correctness call
        cudaStreamCreateWithFlags(&s2, cudaStreamNonBlocking);
        cudaStreamCreateWithFlags(&s3, cudaStreamNonBlocking);
        cudaEventCreateWithFlags(&evF,  cudaEventDisableTiming);
        cudaEventCreateWithFlags(&evJ1, cudaEventDisableTiming);
        cudaEventCreateWithFlags(&evJ3, cudaEventDisableTiming);
        cudaFuncSetAttribute(gemm_fused, cudaFuncAttributeMaxDynamicSharedMemorySize, 2 * STG + 1024);
    }

    float *wtg, *wtu, *wtd;
    cudaGetSymbolAddress((void**)&wtg, g_wtg);
    cudaGetSymbolAddress((void**)&wtu, g_wtu);
    cudaGetSymbolAddress((void**)&wtd, g_wtd);

    // fork
    cudaEventRecord(evF, 0);
    cudaStreamWaitEvent(s2, evF, 0);
    cudaStreamWaitEvent(s3, evF, 0);

    // s2: routing chain + gather
    init_kernel     <<<1, 64, 0, s2>>>();
    route_kernel    <<<TOKENS / 256, 256, 0, s2>>>(logits);
    scan_kernel     <<<1, 32, 0, s2>>>();
    scatter_kernel  <<<NPAIRS / 256, 256, 0, s2>>>();
    gather_kernel   <<<dim3(PBMAX, KT1), 256, 0, s2>>>(hidden);
    cudaEventRecord(evJ1, s2);

    // s3: down-weight tiling
    tile_kernel     <<<dim3(INTER / 64, HIDDEN / 32, NEXP), 256, 0, s3>>>(down, wtd, INTER, HIDDEN, 16, KT2);
    cudaEventRecord(evJ3, s3);

    // main: gate/up tiling
    tile_kernel     <<<dim3(HIDDEN / 64, INTER / 32, NEXP), 256>>>(gate, wtg, HIDDEN, INTER, 6, KT1);
    tile_kernel     <<<dim3(HIDDEN / 64, INTER / 32, NEXP), 256>>>(up,   wtu, HIDDEN, INTER, 6, KT1);

    cudaStreamWaitEvent(0, evJ1, 0);
    cudaStreamWaitEvent(0, evJ3, 0);
    gemm_fused      <<<NBIDS, 256, 2 * STG + 1024>>>(out);
}